// round 3
// baseline (speedup 1.0000x reference)
#include <cuda_runtime.h>
#include <cuda_bf16.h>
#include <cstdint>

// ST-BIF neuron. Round 3: phase-decoupled — load ALL 16 timesteps into
// registers (MLP=16 per thread), run full recurrence in-register, then burst
// all 16 stores. Goal: long same-direction DRAM bursts, fewer R/W turnarounds.

static constexpr int T_STEPS = 16;
static constexpr int B_DIM  = 16;
static constexpr int C_DIM  = 128;
static constexpr int H_DIM  = 32;
static constexpr int W_DIM  = 32;
static constexpr int HW     = H_DIM * W_DIM;                 // 1024
static constexpr int N_ELEM = B_DIM * C_DIM * HW;            // 2,097,152 per timestep
static constexpr int N4     = N_ELEM / 4;                    // 524,288 float4 per timestep
static constexpr int HW4    = HW / 4;                        // 256

static constexpr float TWO_N      = 8.0f;
static constexpr float Q_INIT     = 4.0f;
static constexpr float POS_MAX    = 7.0f;
static constexpr float NEG_MIN    = -8.0f;
static constexpr float BIAS_SCALE = 8.0f / 5.0f;
static constexpr int   BIAS_STEPS = 5;

__device__ __forceinline__ void stbif_step(float& q, float& acc, float inj, float& xio) {
    // Match reference FP order: q = (q + bias) + x
    q = q + inj;
    q = q + xio;
    bool spike = (q - TWO_N >= 0.0f) && (acc < POS_MAX);
    bool neg   = (q < 0.0f)          && (acc > NEG_MIN);
    float cur  = spike ? 1.0f : (neg ? -1.0f : 0.0f);
    acc += cur;
    q   -= TWO_N * cur;
    xio = cur;   // overwrite input register with output spike
}

__global__ __launch_bounds__(256)
void stbif_kernel3(const float4* __restrict__ x,
                   const float*  __restrict__ bias,
                   float4*       __restrict__ out) {
    const int tid = blockIdx.x * blockDim.x + threadIdx.x;   // 0 .. N4-1 (exact grid)
    const int c = (tid / HW4) & (C_DIM - 1);
    const float b4 = __ldg(&bias[c]) * BIAS_SCALE;

    // Phase 1: load all timesteps (16 independent LDG.128)
    float4 v[T_STEPS];
    #pragma unroll
    for (int t = 0; t < T_STEPS; t++) {
        v[t] = __ldcs(&x[(size_t)t * N4 + tid]);
    }

    // Phase 2: full recurrence in registers, outputs overwrite inputs
    float q0 = Q_INIT, q1 = Q_INIT, q2 = Q_INIT, q3 = Q_INIT;
    float a0 = 0.f, a1 = 0.f, a2 = 0.f, a3 = 0.f;
    #pragma unroll
    for (int t = 0; t < T_STEPS; t++) {
        const float inj = (t < BIAS_STEPS) ? b4 : 0.0f;
        stbif_step(q0, a0, inj, v[t].x);
        stbif_step(q1, a1, inj, v[t].y);
        stbif_step(q2, a2, inj, v[t].z);
        stbif_step(q3, a3, inj, v[t].w);
    }

    // Phase 3: burst all stores
    #pragma unroll
    for (int t = 0; t < T_STEPS; t++) {
        __stcs(&out[(size_t)t * N4 + tid], v[t]);
    }
}

extern "C" void kernel_launch(void* const* d_in, const int* in_sizes, int n_in,
                              void* d_out, int out_size) {
    const float4* x    = (const float4*)d_in[0];
    const float*  bias = (const float*)d_in[1];
    float4*       out  = (float4*)d_out;

    const int threads = 256;
    const int blocks  = N4 / threads;   // 2048, exact
    stbif_kernel3<<<blocks, threads>>>(x, bias, out);
}